// round 6
// baseline (speedup 1.0000x reference)
#include <cuda_runtime.h>
#include <cstddef>

#define BB 8
#define TE 2048
#define TD 256
#define HH 128

#define TT 64     // t-tile in score kernel
#define TJ 8      // j-tile in score kernel (one warp per j)
#define WPAD 132  // padded row stride (floats) for Wenc smem tile

#define JT 16     // j-tile in context kernel
#define TC 64     // t-chunk in context kernel

// Scratch for projected tensors (allocation-free per harness rules)
__device__ float g_Wenc[BB * TE * HH];   // 8 MB
__device__ float g_Udec[BB * TD * HH];   // 1 MB

// ---------------------------------------------------------------------------
// Dual tanh via one MUFU op: pack (a,b) -> f16x2, tanh.approx.f16x2, unpack.
// PTX cvt.rn.f16x2.f32 d, a, b puts a in the HIGH half, b in the LOW half.
// f16 quantization + approx error ~3e-4 rms each; attenuated by the V-dot.
// ---------------------------------------------------------------------------
__device__ __forceinline__ void tanh2(float a, float b, float& ta, float& tb) {
    unsigned p;
    asm("cvt.rn.f16x2.f32 %0, %1, %2;" : "=r"(p) : "f"(a), "f"(b));  // hi=a, lo=b
    asm("tanh.approx.f16x2 %0, %0;" : "+r"(p));
    asm("{ .reg .b16 lo, hi;\n\t"
        "  mov.b32 {lo, hi}, %2;\n\t"
        "  cvt.f32.f16 %0, hi;\n\t"
        "  cvt.f32.f16 %1, lo; }"
        : "=f"(ta), "=f"(tb) : "r"(p));
}

// ---------------------------------------------------------------------------
// K0: out[row,k] = sum_h in[row,h] * W[h,k]   (H=128 square projection)
// 16 rows per block, 256 threads; W staged in two 64-row chunks.
// which==0 -> g_Wenc, which==1 -> g_Udec
// ---------------------------------------------------------------------------
__global__ void proj_kernel(const float* __restrict__ in,
                            const float* __restrict__ Wm,
                            int which) {
    __shared__ float Ws[64 * HH];    // 32 KB
    __shared__ float ins[16 * HH];   // 8 KB
    float* out = which ? g_Udec : g_Wenc;

    int tid = threadIdx.x;                  // 256 threads
    int row0 = blockIdx.x * 16;

    // stage 16 input rows (2048 floats = 512 float4)
    const float4* in4 = (const float4*)(in + (size_t)row0 * HH);
    float4* ins4 = (float4*)ins;
    ins4[tid]       = in4[tid];
    ins4[tid + 256] = in4[tid + 256];

    int k = tid & 127;
    int g = tid >> 7;   // 0..1 -> rows g*8 .. g*8+7

    float acc[8];
#pragma unroll
    for (int i = 0; i < 8; i++) acc[i] = 0.0f;

    for (int hc = 0; hc < HH; hc += 64) {
        __syncthreads();
        const float4* W4 = (const float4*)(Wm + hc * HH);
        float4* Ws4 = (float4*)Ws;
#pragma unroll
        for (int i = 0; i < 8; i++) Ws4[tid + i * 256] = W4[tid + i * 256];
        __syncthreads();

#pragma unroll 4
        for (int h = 0; h < 64; h++) {
            float wv = Ws[h * HH + k];            // lanes: consecutive k, conflict-free
#pragma unroll
            for (int i = 0; i < 8; i++)
                acc[i] += ins[(g * 8 + i) * HH + hc + h] * wv;   // broadcast
        }
    }

#pragma unroll
    for (int i = 0; i < 8; i++)
        out[(size_t)(row0 + g * 8 + i) * HH + k] = acc[i];
}

// ---------------------------------------------------------------------------
// K1: raw scores s[b,j,t] = sum_k V[k]*tanh(Wenc[b,t,k]+Udec[b,j,k])
// Grid (TE/TT, TD/TJ, B). 256 threads = 8 warps; warp w owns j = jb*TJ + w,
// lanes cover t = lane and lane+32 within a 64-t tile.
// The two t-elements per lane are evaluated with ONE tanh.approx.f16x2.
// Writes raw scores into the e-output region (softmaxed in place by K2).
// ---------------------------------------------------------------------------
__global__ void score_kernel(const float* __restrict__ Va,
                             float* __restrict__ e_out) {
    __shared__ float We[TT * WPAD];   // 33 KB
    __shared__ float Ud[TJ * HH];     // 4 KB
    __shared__ float Vs[HH];          // 0.5 KB

    int tid = threadIdx.x;            // 256
    int b  = blockIdx.z;
    int jb = blockIdx.y;
    int tb = blockIdx.x;

    // stage Wenc tile [TT x H] with padded rows
    {
        const float4* src = (const float4*)(g_Wenc + ((size_t)b * TE + tb * TT) * HH);
        float4* We4 = (float4*)We;
#pragma unroll
        for (int i = 0; i < (TT * HH / 4) / 256; i++) {   // 8 iters
            int idx = tid + i * 256;        // float4 index over [TT][32]
            int r = idx >> 5, c = idx & 31;
            We4[r * (WPAD / 4) + c] = src[idx];
        }
    }
    // stage Udec tile [TJ x H]: exactly 256 float4
    {
        const float4* usrc = (const float4*)(g_Udec + ((size_t)b * TD + jb * TJ) * HH);
        ((float4*)Ud)[tid] = usrc[tid];
    }
    if (tid < HH / 4) ((float4*)Vs)[tid] = ((const float4*)Va)[tid];
    __syncthreads();

    int w = tid >> 5;      // warp index = local j
    int lane = tid & 31;

    const float4* urow = (const float4*)(Ud + w * HH);
    const float4* Wr0  = (const float4*)We + (size_t)lane * (WPAD / 4);
    const float4* Wr1  = Wr0 + 32 * (WPAD / 4);
    const float4* V4   = (const float4*)Vs;

    float acc0 = 0.0f, acc1 = 0.0f;
#pragma unroll 8
    for (int k4 = 0; k4 < HH / 4; k4++) {
        float4 vv = V4[k4];
        float4 uu = urow[k4];
        float4 w0 = Wr0[k4];
        float4 w1 = Wr1[k4];
        float t0, t1;
        tanh2(w0.x + uu.x, w1.x + uu.x, t0, t1);
        acc0 += vv.x * t0;  acc1 += vv.x * t1;
        tanh2(w0.y + uu.y, w1.y + uu.y, t0, t1);
        acc0 += vv.y * t0;  acc1 += vv.y * t1;
        tanh2(w0.z + uu.z, w1.z + uu.z, t0, t1);
        acc0 += vv.z * t0;  acc1 += vv.z * t1;
        tanh2(w0.w + uu.w, w1.w + uu.w, t0, t1);
        acc0 += vv.w * t0;  acc1 += vv.w * t1;
    }

    int j  = jb * TJ + w;
    int t0i = tb * TT + lane;
    size_t base = ((size_t)b * TD + j) * TE;
    e_out[base + t0i]      = acc0;
    e_out[base + t0i + 32] = acc1;
}

// ---------------------------------------------------------------------------
// K2: in-place softmax over the last axis (TE=2048) of e. One block per row.
// ---------------------------------------------------------------------------
__global__ void softmax_kernel(float* __restrict__ e) {
    __shared__ float red[8];
    int row = blockIdx.x;
    float* p = e + (size_t)row * TE;
    int tid = threadIdx.x;   // 256

    float4* p4 = (float4*)p;
    float4 v0 = p4[tid];
    float4 v1 = p4[tid + 256];

    float m = fmaxf(fmaxf(fmaxf(v0.x, v0.y), fmaxf(v0.z, v0.w)),
                    fmaxf(fmaxf(v1.x, v1.y), fmaxf(v1.z, v1.w)));
#pragma unroll
    for (int o = 16; o; o >>= 1) m = fmaxf(m, __shfl_xor_sync(0xffffffffu, m, o));
    if ((tid & 31) == 0) red[tid >> 5] = m;
    __syncthreads();
    m = red[0];
#pragma unroll
    for (int i = 1; i < 8; i++) m = fmaxf(m, red[i]);
    __syncthreads();

    v0.x = __expf(v0.x - m); v0.y = __expf(v0.y - m);
    v0.z = __expf(v0.z - m); v0.w = __expf(v0.w - m);
    v1.x = __expf(v1.x - m); v1.y = __expf(v1.y - m);
    v1.z = __expf(v1.z - m); v1.w = __expf(v1.w - m);

    float s = ((v0.x + v0.y) + (v0.z + v0.w)) + ((v1.x + v1.y) + (v1.z + v1.w));
#pragma unroll
    for (int o = 16; o; o >>= 1) s += __shfl_xor_sync(0xffffffffu, s, o);
    if ((tid & 31) == 0) red[tid >> 5] = s;
    __syncthreads();
    s = red[0];
#pragma unroll
    for (int i = 1; i < 8; i++) s += red[i];

    float inv = __fdividef(1.0f, s);
    v0.x *= inv; v0.y *= inv; v0.z *= inv; v0.w *= inv;
    v1.x *= inv; v1.y *= inv; v1.z *= inv; v1.w *= inv;
    p4[tid]       = v0;
    p4[tid + 256] = v1;
}

// ---------------------------------------------------------------------------
// K3: c[b,j,h] = sum_t e[b,j,t] * enc[b,t,h]
// One block per (b, 16-j tile). enc staged in 64-t chunks (32KB smem).
// Thread: h = tid&127, owns 8 j's (jg = tid>>7 selects which 8).
// ---------------------------------------------------------------------------
__global__ void context_kernel(const float* __restrict__ enc,
                               const float* __restrict__ e,
                               float* __restrict__ c) {
    __shared__ float encs[TC * HH];   // 32 KB
    __shared__ float es[JT * TC];     // 4 KB

    int tid = threadIdx.x;            // 256
    int bj = blockIdx.x;              // 0 .. B*TD/JT-1
    int b  = bj / (TD / JT);
    int jb = bj % (TD / JT);

    int h  = tid & 127;
    int jg = tid >> 7;                // 0..1

    float acc[8];
#pragma unroll
    for (int i = 0; i < 8; i++) acc[i] = 0.0f;

    for (int tc = 0; tc < TE; tc += TC) {
        __syncthreads();
        // stage enc[b, tc:tc+TC, :]  (2048 float4)
        {
            const float4* src = (const float4*)(enc + ((size_t)b * TE + tc) * HH);
            float4* d4 = (float4*)encs;
#pragma unroll
            for (int i = 0; i < 8; i++) d4[tid + i * 256] = src[tid + i * 256];
        }
        // stage e[b, jb*JT + jj, tc:tc+TC]  (256 float4)
        {
            int jj = tid >> 4, c4 = tid & 15;
            ((float4*)es)[tid] =
                ((const float4*)(e + (((size_t)b * TD + jb * JT + jj) * TE + tc)))[c4];
        }
        __syncthreads();

#pragma unroll 4
        for (int t4 = 0; t4 < TC / 4; t4++) {
            float en0 = encs[(t4 * 4 + 0) * HH + h];
            float en1 = encs[(t4 * 4 + 1) * HH + h];
            float en2 = encs[(t4 * 4 + 2) * HH + h];
            float en3 = encs[(t4 * 4 + 3) * HH + h];
#pragma unroll
            for (int i = 0; i < 8; i++) {
                float4 ev = ((const float4*)es)[(jg * 8 + i) * (TC / 4) + t4];
                acc[i] += ev.x * en0 + ev.y * en1 + ev.z * en2 + ev.w * en3;
            }
        }
    }

    int jbase = b * TD + jb * JT + jg * 8;
#pragma unroll
    for (int i = 0; i < 8; i++)
        c[(size_t)(jbase + i) * HH + h] = acc[i];
}

// ---------------------------------------------------------------------------
// Launch: c_outputs [B,TD,H] then e_outputs [B,TD,TE], flattened in order.
// ---------------------------------------------------------------------------
extern "C" void kernel_launch(void* const* d_in, const int* in_sizes, int n_in,
                              void* d_out, int out_size) {
    const float* enc = (const float*)d_in[0];   // [B,TE,H]
    const float* dec = (const float*)d_in[1];   // [B,TD,D]
    const float* Wa  = (const float*)d_in[2];   // [H,H]
    const float* Ua  = (const float*)d_in[3];   // [D,H]
    const float* Va  = (const float*)d_in[4];   // [H,1]

    float* out   = (float*)d_out;
    float* c_out = out;                          // B*TD*H
    float* e_out = out + (size_t)BB * TD * HH;   // B*TD*TE

    proj_kernel<<<BB * TE / 16, 256>>>(enc, Wa, 0);
    proj_kernel<<<BB * TD / 16, 256>>>(dec, Ua, 1);
    score_kernel<<<dim3(TE / TT, TD / TJ, BB), 256>>>(Va, e_out);
    softmax_kernel<<<BB * TD, 256>>>(e_out);
    context_kernel<<<BB * TD / JT, 256>>>(enc, e_out, c_out);
}

// round 7
// speedup vs baseline: 1.0116x; 1.0116x over previous
#include <cuda_runtime.h>
#include <cstddef>
#include <cstdint>

#define BB 8
#define TE 2048
#define TD 256
#define HH 128

#define TT 64     // t-tile in score kernel
#define TJ 8      // j-tile in score kernel (one warp per j)

#define JT 16     // j-tile in context kernel
#define TC 64     // t-chunk in context kernel

// Scratch (allocation-free per harness rules)
// Wenc in f16, tiled layout: [b][tb=t/64][k][tl=t%64] halves -> 4 MB
__device__ unsigned short g_WencH[BB * TE * HH];
// Udec duplicated half2(u,u): [b][j][k] -> 1 MB
__device__ unsigned g_UdecH[BB * TD * HH];

// ---------------------------------------------------------------------------
// K0: projection out[row,k] = sum_h in[row,h] * W[h,k]  (f32 accumulate),
// emitted as f16 in the layouts the score kernel wants.
// which==0 -> g_WencH (tiled), which==1 -> g_UdecH (duplicated half2)
// ---------------------------------------------------------------------------
__global__ void proj_kernel(const float* __restrict__ in,
                            const float* __restrict__ Wm,
                            int which) {
    __shared__ float Ws[64 * HH];    // 32 KB
    __shared__ float ins[16 * HH];   // 8 KB

    int tid = threadIdx.x;                  // 256 threads
    int row0 = blockIdx.x * 16;

    const float4* in4 = (const float4*)(in + (size_t)row0 * HH);
    float4* ins4 = (float4*)ins;
    ins4[tid]       = in4[tid];
    ins4[tid + 256] = in4[tid + 256];

    int k = tid & 127;
    int g = tid >> 7;   // rows g*8 .. g*8+7

    float acc[8];
#pragma unroll
    for (int i = 0; i < 8; i++) acc[i] = 0.0f;

    for (int hc = 0; hc < HH; hc += 64) {
        __syncthreads();
        const float4* W4 = (const float4*)(Wm + hc * HH);
        float4* Ws4 = (float4*)Ws;
#pragma unroll
        for (int i = 0; i < 8; i++) Ws4[tid + i * 256] = W4[tid + i * 256];
        __syncthreads();

#pragma unroll 4
        for (int h = 0; h < 64; h++) {
            float wv = Ws[h * HH + k];
#pragma unroll
            for (int i = 0; i < 8; i++)
                acc[i] += ins[(g * 8 + i) * HH + hc + h] * wv;
        }
    }

    int r0 = row0 + g * 8;        // 8 consecutive global rows, same b, same 64-tile
    if (which == 0) {
        // pack 8 consecutive-t halves (memory order: lo = lower t)
        unsigned u[4];
#pragma unroll
        for (int m = 0; m < 4; m++)
            asm("cvt.rn.f16x2.f32 %0, %1, %2;"
                : "=r"(u[m]) : "f"(acc[2 * m + 1]), "f"(acc[2 * m]));  // hi=odd, lo=even
        int b  = r0 / TE;
        int t  = r0 % TE;
        int tb = t / 64;
        int tl0 = t % 64;
        unsigned short* dst = g_WencH +
            ((size_t)(b * (TE / 64) + tb) * HH + k) * 64 + tl0;
        *(uint4*)dst = make_uint4(u[0], u[1], u[2], u[3]);   // 16B aligned (tl0 % 8 == 0)
    } else {
#pragma unroll
        for (int i = 0; i < 8; i++) {
            unsigned d;
            asm("cvt.rn.f16x2.f32 %0, %1, %1;" : "=r"(d) : "f"(acc[i]));  // (u,u)
            g_UdecH[(size_t)(r0 + i) * HH + k] = d;
        }
    }
}

// ---------------------------------------------------------------------------
// K1: raw scores s[b,j,t] = sum_k V[k]*tanh(Wenc[b,t,k]+Udec[b,j,k])
// All-f16 hot loop: HADD2 + tanh.approx.f16x2 per t-pair; f32x2 accumulate.
// Warp w owns j; lane l owns t = tb*64 + {2l, 2l+1}.
// ---------------------------------------------------------------------------
__global__ void score_kernel(const float* __restrict__ Va,
                             float* __restrict__ e_out) {
    __shared__ __align__(16) unsigned short Weh[TT * HH];  // [k][64] halves, 16 KB
    __shared__ __align__(16) unsigned Udh[TJ * HH];        // [j][k] dup half2, 4 KB
    __shared__ __align__(16) float2 Vs2[HH];               // (v,v) pairs, 1 KB

    int tid = threadIdx.x;            // 256
    int b  = blockIdx.z;
    int jb = blockIdx.y;
    int tb = blockIdx.x;

    // stage Wenc tile: straight 16KB copy (layout matches smem exactly)
    {
        const uint4* src = (const uint4*)(g_WencH +
            (size_t)(b * (TE / 64) + tb) * (HH * 64));
        uint4* dst = (uint4*)Weh;
#pragma unroll
        for (int i = 0; i < 4; i++) dst[tid + i * 256] = src[tid + i * 256];
    }
    // stage Udec tile: 8 j x 128 k uints = 256 uint4
    {
        const uint4* us = (const uint4*)(g_UdecH + ((size_t)b * TD + jb * TJ) * HH);
        ((uint4*)Udh)[tid] = us[tid];
    }
    if (tid < HH) { float v = Va[tid]; Vs2[tid] = make_float2(v, v); }
    __syncthreads();

    int w = tid >> 5;      // local j
    int lane = tid & 31;

    const unsigned* Wp = (const unsigned*)Weh + lane;   // + k*32 per k
    const unsigned* Up = Udh + w * HH;

    unsigned long long acc01 = 0ull;   // packed f32x2 (even-t, odd-t)

#pragma unroll 4
    for (int k = 0; k < HH; k++) {
        unsigned wx = Wp[k * 32];      // (t=2l, t=2l+1) halves
        unsigned ux = Up[k];           // (u, u)
        unsigned x2;
        asm("add.rn.f16x2 %0, %1, %2;" : "=r"(x2) : "r"(wx), "r"(ux));
        asm("tanh.approx.f16x2 %0, %0;" : "+r"(x2));
        float flo, fhi;
        asm("{ .reg .b16 lo, hi;\n\t"
            "  mov.b32 {lo, hi}, %2;\n\t"
            "  cvt.f32.f16 %0, lo;\n\t"
            "  cvt.f32.f16 %1, hi; }"
            : "=f"(flo), "=f"(fhi) : "r"(x2));
        unsigned long long t01, v2;
        asm("mov.b64 %0, {%1, %2};" : "=l"(t01) : "f"(flo), "f"(fhi));
        v2 = *(const unsigned long long*)&Vs2[k];
        asm("fma.rn.f32x2 %0, %1, %2, %0;" : "+l"(acc01) : "l"(t01), "l"(v2));
    }

    float ae, ao;
    asm("mov.b64 {%0, %1}, %2;" : "=f"(ae), "=f"(ao) : "l"(acc01));

    int j = jb * TJ + w;
    size_t base = ((size_t)b * TD + j) * TE + tb * TT;
    *(float2*)(e_out + base + 2 * lane) = make_float2(ae, ao);
}

// ---------------------------------------------------------------------------
// K2: in-place softmax over the last axis (TE=2048) of e. One block per row.
// ---------------------------------------------------------------------------
__global__ void softmax_kernel(float* __restrict__ e) {
    __shared__ float red[8];
    int row = blockIdx.x;
    float* p = e + (size_t)row * TE;
    int tid = threadIdx.x;   // 256

    float4* p4 = (float4*)p;
    float4 v0 = p4[tid];
    float4 v1 = p4[tid + 256];

    float m = fmaxf(fmaxf(fmaxf(v0.x, v0.y), fmaxf(v0.z, v0.w)),
                    fmaxf(fmaxf(v1.x, v1.y), fmaxf(v1.z, v1.w)));
#pragma unroll
    for (int o = 16; o; o >>= 1) m = fmaxf(m, __shfl_xor_sync(0xffffffffu, m, o));
    if ((tid & 31) == 0) red[tid >> 5] = m;
    __syncthreads();
    m = red[0];
#pragma unroll
    for (int i = 1; i < 8; i++) m = fmaxf(m, red[i]);
    __syncthreads();

    v0.x = __expf(v0.x - m); v0.y = __expf(v0.y - m);
    v0.z = __expf(v0.z - m); v0.w = __expf(v0.w - m);
    v1.x = __expf(v1.x - m); v1.y = __expf(v1.y - m);
    v1.z = __expf(v1.z - m); v1.w = __expf(v1.w - m);

    float s = ((v0.x + v0.y) + (v0.z + v0.w)) + ((v1.x + v1.y) + (v1.z + v1.w));
#pragma unroll
    for (int o = 16; o; o >>= 1) s += __shfl_xor_sync(0xffffffffu, s, o);
    if ((tid & 31) == 0) red[tid >> 5] = s;
    __syncthreads();
    s = red[0];
#pragma unroll
    for (int i = 1; i < 8; i++) s += red[i];

    float inv = __fdividef(1.0f, s);
    v0.x *= inv; v0.y *= inv; v0.z *= inv; v0.w *= inv;
    v1.x *= inv; v1.y *= inv; v1.z *= inv; v1.w *= inv;
    p4[tid]       = v0;
    p4[tid + 256] = v1;
}

// ---------------------------------------------------------------------------
// K3: c[b,j,h] = sum_t e[b,j,t] * enc[b,t,h]
// ---------------------------------------------------------------------------
__global__ void context_kernel(const float* __restrict__ enc,
                               const float* __restrict__ e,
                               float* __restrict__ c) {
    __shared__ float encs[TC * HH];   // 32 KB
    __shared__ float es[JT * TC];     // 4 KB

    int tid = threadIdx.x;            // 256
    int bj = blockIdx.x;
    int b  = bj / (TD / JT);
    int jb = bj % (TD / JT);

    int h  = tid & 127;
    int jg = tid >> 7;

    float acc[8];
#pragma unroll
    for (int i = 0; i < 8; i++) acc[i] = 0.0f;

    for (int tc = 0; tc < TE; tc += TC) {
        __syncthreads();
        {
            const float4* src = (const float4*)(enc + ((size_t)b * TE + tc) * HH);
            float4* d4 = (float4*)encs;
#pragma unroll
            for (int i = 0; i < 8; i++) d4[tid + i * 256] = src[tid + i * 256];
        }
        {
            int jj = tid >> 4, c4 = tid & 15;
            ((float4*)es)[tid] =
                ((const float4*)(e + (((size_t)b * TD + jb * JT + jj) * TE + tc)))[c4];
        }
        __syncthreads();

#pragma unroll 4
        for (int t4 = 0; t4 < TC / 4; t4++) {
            float en0 = encs[(t4 * 4 + 0) * HH + h];
            float en1 = encs[(t4 * 4 + 1) * HH + h];
            float en2 = encs[(t4 * 4 + 2) * HH + h];
            float en3 = encs[(t4 * 4 + 3) * HH + h];
#pragma unroll
            for (int i = 0; i < 8; i++) {
                float4 ev = ((const float4*)es)[(jg * 8 + i) * (TC / 4) + t4];
                acc[i] += ev.x * en0 + ev.y * en1 + ev.z * en2 + ev.w * en3;
            }
        }
    }

    int jbase = b * TD + jb * JT + jg * 8;
#pragma unroll
    for (int i = 0; i < 8; i++)
        c[(size_t)(jbase + i) * HH + h] = acc[i];
}

// ---------------------------------------------------------------------------
// Launch: c_outputs [B,TD,H] then e_outputs [B,TD,TE], flattened in order.
// ---------------------------------------------------------------------------
extern "C" void kernel_launch(void* const* d_in, const int* in_sizes, int n_in,
                              void* d_out, int out_size) {
    const float* enc = (const float*)d_in[0];   // [B,TE,H]
    const float* dec = (const float*)d_in[1];   // [B,TD,D]
    const float* Wa  = (const float*)d_in[2];   // [H,H]
    const float* Ua  = (const float*)d_in[3];   // [D,H]
    const float* Va  = (const float*)d_in[4];   // [H,1]

    float* out   = (float*)d_out;
    float* c_out = out;                          // B*TD*H
    float* e_out = out + (size_t)BB * TD * HH;   // B*TD*TE

    proj_kernel<<<BB * TE / 16, 256>>>(enc, Wa, 0);
    proj_kernel<<<BB * TD / 16, 256>>>(dec, Ua, 1);
    score_kernel<<<dim3(TE / TT, TD / TJ, BB), 256>>>(Va, e_out);
    softmax_kernel<<<BB * TD, 256>>>(e_out);
    context_kernel<<<BB * TD / JT, 256>>>(enc, e_out, c_out);
}

// round 8
// speedup vs baseline: 1.1236x; 1.1107x over previous
#include <cuda_runtime.h>
#include <cstddef>
#include <cstdint>

#define BB 8
#define TE 2048
#define TD 256
#define HH 128

#define TT 64     // t-tile in score kernel
#define TJ 8      // j-tile in score kernel (one warp per j)

#define JT 16     // j-tile in context kernel
#define TC 64     // t-chunk in context kernel

typedef unsigned long long ull;

// Scratch (allocation-free per harness rules)
// Wenc in f16, tiled layout: [b][tb=t/64][k][tl=t%64] halves -> 4 MB
__device__ unsigned short g_WencH[BB * TE * HH];
// Udec duplicated half2(u,u): [b][j][k] -> 1 MB
__device__ unsigned g_UdecH[BB * TD * HH];

__device__ __forceinline__ void fma2(ull& acc, ull a, ull b) {
    asm("fma.rn.f32x2 %0, %1, %2, %0;" : "+l"(acc) : "l"(a), "l"(b));
}
__device__ __forceinline__ ull pack2(float lo, float hi) {
    ull r; asm("mov.b64 %0, {%1, %2};" : "=l"(r) : "f"(lo), "f"(hi)); return r;
}
__device__ __forceinline__ void unpack2(ull v, float& lo, float& hi) {
    asm("mov.b64 {%0, %1}, %2;" : "=f"(lo), "=f"(hi) : "l"(v));
}

// ---------------------------------------------------------------------------
// K0: out[row,k] = sum_h in[row,h] * W[h,k]  (f32 accumulate, FFMA2 over
// k-pairs), emitted as f16 in the layouts the score kernel wants.
// 256 threads: k2 = tid&63 (k pair), g = tid>>6 (4 rows each); 16 rows/block.
// which==0 -> g_WencH (tiled), which==1 -> g_UdecH (duplicated half2)
// ---------------------------------------------------------------------------
__global__ void proj_kernel(const float* __restrict__ in,
                            const float* __restrict__ Wm,
                            int which) {
    __shared__ float Ws[64 * HH];    // 32 KB
    __shared__ float ins[16 * HH];   // 8 KB

    int tid = threadIdx.x;                  // 256 threads
    int row0 = blockIdx.x * 16;

    const float4* in4 = (const float4*)(in + (size_t)row0 * HH);
    float4* ins4 = (float4*)ins;
    ins4[tid]       = in4[tid];
    ins4[tid + 256] = in4[tid + 256];

    int k2 = tid & 63;    // k = {2k2, 2k2+1}
    int g  = tid >> 6;    // rows g*4 .. g*4+3

    ull acc[4] = {0ull, 0ull, 0ull, 0ull};   // 4 rows x f32x2 (k-even, k-odd)

    for (int hc = 0; hc < HH; hc += 64) {
        __syncthreads();
        const float4* W4 = (const float4*)(Wm + hc * HH);
        float4* Ws4 = (float4*)Ws;
#pragma unroll
        for (int i = 0; i < 8; i++) Ws4[tid + i * 256] = W4[tid + i * 256];
        __syncthreads();

#pragma unroll 4
        for (int h4 = 0; h4 < 64; h4 += 4) {
            float4 iv0 = *(const float4*)&ins[(g * 4 + 0) * HH + hc + h4];
            float4 iv1 = *(const float4*)&ins[(g * 4 + 1) * HH + hc + h4];
            float4 iv2 = *(const float4*)&ins[(g * 4 + 2) * HH + hc + h4];
            float4 iv3 = *(const float4*)&ins[(g * 4 + 3) * HH + hc + h4];
#pragma unroll
            for (int dh = 0; dh < 4; dh++) {
                ull wv2 = *(const ull*)&Ws[(h4 + dh) * HH + 2 * k2];  // LDS.64
                float e0 = (&iv0.x)[dh], e1 = (&iv1.x)[dh];
                float e2 = (&iv2.x)[dh], e3 = (&iv3.x)[dh];
                fma2(acc[0], wv2, pack2(e0, e0));
                fma2(acc[1], wv2, pack2(e1, e1));
                fma2(acc[2], wv2, pack2(e2, e2));
                fma2(acc[3], wv2, pack2(e3, e3));
            }
        }
    }

    float ax[4], ay[4];
#pragma unroll
    for (int i = 0; i < 4; i++) unpack2(acc[i], ax[i], ay[i]);

    int r0 = row0 + g * 4;   // 4 consecutive rows (t or j), same b, same 64-tile
    if (which == 0) {
        int b   = r0 / TE;
        int t   = r0 % TE;
        int tb  = t / 64;
        int tl0 = t % 64;    // multiple of 4
        // per k: 4 consecutive-t halves (lo half = lower t)
        unsigned ex0, ex1, ey0, ey1;
        asm("cvt.rn.f16x2.f32 %0, %1, %2;" : "=r"(ex0) : "f"(ax[1]), "f"(ax[0]));
        asm("cvt.rn.f16x2.f32 %0, %1, %2;" : "=r"(ex1) : "f"(ax[3]), "f"(ax[2]));
        asm("cvt.rn.f16x2.f32 %0, %1, %2;" : "=r"(ey0) : "f"(ay[1]), "f"(ay[0]));
        asm("cvt.rn.f16x2.f32 %0, %1, %2;" : "=r"(ey1) : "f"(ay[3]), "f"(ay[2]));
        size_t base = (size_t)(b * (TE / 64) + tb) * HH * 64;
        *(uint2*)(g_WencH + base + (size_t)(2 * k2 + 0) * 64 + tl0) = make_uint2(ex0, ex1);
        *(uint2*)(g_WencH + base + (size_t)(2 * k2 + 1) * 64 + tl0) = make_uint2(ey0, ey1);
    } else {
#pragma unroll
        for (int i = 0; i < 4; i++) {
            unsigned d0, d1;
            asm("cvt.rn.f16x2.f32 %0, %1, %1;" : "=r"(d0) : "f"(ax[i]));  // (u,u)
            asm("cvt.rn.f16x2.f32 %0, %1, %1;" : "=r"(d1) : "f"(ay[i]));
            *(uint2*)(g_UdecH + (size_t)(r0 + i) * HH + 2 * k2) = make_uint2(d0, d1);
        }
    }
}

// ---------------------------------------------------------------------------
// K1: raw scores s[b,j,t] = sum_k V[k]*tanh(Wenc[b,t,k]+Udec[b,j,k])
// All-f16 hot loop: HADD2 + tanh.approx.f16x2 per t-pair; f32x2 accumulate.
// Warp w owns j; lane l owns t = tb*64 + {2l, 2l+1}.  (MUFU-pinned ~126us)
// ---------------------------------------------------------------------------
__global__ void score_kernel(const float* __restrict__ Va,
                             float* __restrict__ e_out) {
    __shared__ __align__(16) unsigned short Weh[TT * HH];  // [k][64] halves, 16 KB
    __shared__ __align__(16) unsigned Udh[TJ * HH];        // [j][k] dup half2, 4 KB
    __shared__ __align__(16) float2 Vs2[HH];               // (v,v) pairs, 1 KB

    int tid = threadIdx.x;            // 256
    int b  = blockIdx.z;
    int jb = blockIdx.y;
    int tb = blockIdx.x;

    // stage Wenc tile: straight 16KB copy (layout matches smem exactly)
    {
        const uint4* src = (const uint4*)(g_WencH +
            (size_t)(b * (TE / 64) + tb) * (HH * 64));
        uint4* dst = (uint4*)Weh;
#pragma unroll
        for (int i = 0; i < 4; i++) dst[tid + i * 256] = src[tid + i * 256];
    }
    // stage Udec tile: 8 j x 128 k uints = 256 uint4
    {
        const uint4* us = (const uint4*)(g_UdecH + ((size_t)b * TD + jb * TJ) * HH);
        ((uint4*)Udh)[tid] = us[tid];
    }
    if (tid < HH) { float v = Va[tid]; Vs2[tid] = make_float2(v, v); }
    __syncthreads();

    int w = tid >> 5;      // local j
    int lane = tid & 31;

    const unsigned* Wp = (const unsigned*)Weh + lane;   // + k*32 per k
    const unsigned* Up = Udh + w * HH;

    ull acc01 = 0ull;   // packed f32x2 (even-t, odd-t)

#pragma unroll 4
    for (int k = 0; k < HH; k++) {
        unsigned wx = Wp[k * 32];      // (t=2l, t=2l+1) halves
        unsigned ux = Up[k];           // (u, u)
        unsigned x2;
        asm("add.rn.f16x2 %0, %1, %2;" : "=r"(x2) : "r"(wx), "r"(ux));
        asm("tanh.approx.f16x2 %0, %0;" : "+r"(x2));
        float flo, fhi;
        asm("{ .reg .b16 lo, hi;\n\t"
            "  mov.b32 {lo, hi}, %2;\n\t"
            "  cvt.f32.f16 %0, lo;\n\t"
            "  cvt.f32.f16 %1, hi; }"
            : "=f"(flo), "=f"(fhi) : "r"(x2));
        fma2(acc01, pack2(flo, fhi), *(const ull*)&Vs2[k]);
    }

    float ae, ao;
    unpack2(acc01, ae, ao);

    int j = jb * TJ + w;
    size_t base = ((size_t)b * TD + j) * TE + tb * TT;
    *(float2*)(e_out + base + 2 * lane) = make_float2(ae, ao);
}

// ---------------------------------------------------------------------------
// K2: in-place softmax over the last axis (TE=2048) of e. One block per row.
// ---------------------------------------------------------------------------
__global__ void softmax_kernel(float* __restrict__ e) {
    __shared__ float red[8];
    int row = blockIdx.x;
    float* p = e + (size_t)row * TE;
    int tid = threadIdx.x;   // 256

    float4* p4 = (float4*)p;
    float4 v0 = p4[tid];
    float4 v1 = p4[tid + 256];

    float m = fmaxf(fmaxf(fmaxf(v0.x, v0.y), fmaxf(v0.z, v0.w)),
                    fmaxf(fmaxf(v1.x, v1.y), fmaxf(v1.z, v1.w)));
#pragma unroll
    for (int o = 16; o; o >>= 1) m = fmaxf(m, __shfl_xor_sync(0xffffffffu, m, o));
    if ((tid & 31) == 0) red[tid >> 5] = m;
    __syncthreads();
    m = red[0];
#pragma unroll
    for (int i = 1; i < 8; i++) m = fmaxf(m, red[i]);
    __syncthreads();

    v0.x = __expf(v0.x - m); v0.y = __expf(v0.y - m);
    v0.z = __expf(v0.z - m); v0.w = __expf(v0.w - m);
    v1.x = __expf(v1.x - m); v1.y = __expf(v1.y - m);
    v1.z = __expf(v1.z - m); v1.w = __expf(v1.w - m);

    float s = ((v0.x + v0.y) + (v0.z + v0.w)) + ((v1.x + v1.y) + (v1.z + v1.w));
#pragma unroll
    for (int o = 16; o; o >>= 1) s += __shfl_xor_sync(0xffffffffu, s, o);
    if ((tid & 31) == 0) red[tid >> 5] = s;
    __syncthreads();
    s = red[0];
#pragma unroll
    for (int i = 1; i < 8; i++) s += red[i];

    float inv = __fdividef(1.0f, s);
    v0.x *= inv; v0.y *= inv; v0.z *= inv; v0.w *= inv;
    v1.x *= inv; v1.y *= inv; v1.z *= inv; v1.w *= inv;
    p4[tid]       = v0;
    p4[tid + 256] = v1;
}

// ---------------------------------------------------------------------------
// K3: c[b,j,h] = sum_t e[b,j,t] * enc[b,t,h]
// 256 threads: warp -> (ts = wid>>2 t-half, jg = wid&3), lane -> h4 (4 h).
// Register tile 4j x 4h, FFMA2 math, e loads are float4 broadcasts.
// 2-way t-split reduced through smem at the end.
// ---------------------------------------------------------------------------
__global__ void context_kernel(const float* __restrict__ enc,
                               const float* __restrict__ e,
                               float* __restrict__ c) {
    __shared__ float encs[TC * HH];   // 32 KB (reused for reduction)
    __shared__ float es[JT * TC];     // 4 KB

    int tid = threadIdx.x;            // 256
    int bj = blockIdx.x;              // 0 .. B*TD/JT-1
    int b  = bj >> 4;                 // TD/JT = 16
    int jb = bj & 15;

    int wid  = tid >> 5;
    int lane = tid & 31;
    int ts   = wid >> 2;              // 0..1 t-half
    int jg   = wid & 3;               // 0..3 (4 j each)

    ull acc[4][2];                    // [j][h-pair]: (4lane,4lane+1),(4lane+2,4lane+3)
#pragma unroll
    for (int j = 0; j < 4; j++) { acc[j][0] = 0ull; acc[j][1] = 0ull; }

    for (int tc = 0; tc < TE; tc += TC) {
        __syncthreads();
        {
            const float4* src = (const float4*)(enc + ((size_t)b * TE + tc) * HH);
            float4* d4 = (float4*)encs;
#pragma unroll
            for (int i = 0; i < 8; i++) d4[tid + i * 256] = src[tid + i * 256];
        }
        {
            int jj = tid >> 4, c4 = tid & 15;
            ((float4*)es)[tid] =
                ((const float4*)(e + (((size_t)b * TD + jb * JT + jj) * TE + tc)))[c4];
        }
        __syncthreads();

        const float4* es4   = (const float4*)es;
        const float4* encs4 = (const float4*)encs;
#pragma unroll 2
        for (int t0 = ts * 32; t0 < ts * 32 + 32; t0 += 4) {
            float4 ev0 = es4[(jg * 4 + 0) * 16 + (t0 >> 2)];   // broadcast
            float4 ev1 = es4[(jg * 4 + 1) * 16 + (t0 >> 2)];
            float4 ev2 = es4[(jg * 4 + 2) * 16 + (t0 >> 2)];
            float4 ev3 = es4[(jg * 4 + 3) * 16 + (t0 >> 2)];
#pragma unroll
            for (int dt = 0; dt < 4; dt++) {
                float4 en = encs4[(t0 + dt) * 32 + lane];
                ull en01 = pack2(en.x, en.y);
                ull en23 = pack2(en.z, en.w);
                float e0 = (&ev0.x)[dt], e1 = (&ev1.x)[dt];
                float e2 = (&ev2.x)[dt], e3 = (&ev3.x)[dt];
                ull ee;
                ee = pack2(e0, e0); fma2(acc[0][0], en01, ee); fma2(acc[0][1], en23, ee);
                ee = pack2(e1, e1); fma2(acc[1][0], en01, ee); fma2(acc[1][1], en23, ee);
                ee = pack2(e2, e2); fma2(acc[2][0], en01, ee); fma2(acc[2][1], en23, ee);
                ee = pack2(e3, e3); fma2(acc[3][0], en01, ee); fma2(acc[3][1], en23, ee);
            }
        }
    }

    // 2-way t-split reduction via smem (reuse encs; 128 threads x 16 floats)
    __syncthreads();
    if (ts == 1) {
        float* dst = encs + (size_t)(wid & 3) * 32 * 16 + lane * 16;  // per (jg,lane)
#pragma unroll
        for (int j = 0; j < 4; j++) {
            unpack2(acc[j][0], dst[j * 4 + 0], dst[j * 4 + 1]);
            unpack2(acc[j][1], dst[j * 4 + 2], dst[j * 4 + 3]);
        }
    }
    __syncthreads();
    if (ts == 0) {
        const float* src = encs + (size_t)jg * 32 * 16 + lane * 16;
        int jbase = (b * TD + jb * JT + jg * 4);
#pragma unroll
        for (int j = 0; j < 4; j++) {
            float x0, x1, x2, x3;
            unpack2(acc[j][0], x0, x1);
            unpack2(acc[j][1], x2, x3);
            float4 r = make_float4(x0 + src[j * 4 + 0], x1 + src[j * 4 + 1],
                                   x2 + src[j * 4 + 2], x3 + src[j * 4 + 3]);
            *(float4*)(c + (size_t)(jbase + j) * HH + 4 * lane) = r;
        }
    }
}

// ---------------------------------------------------------------------------
// Launch: c_outputs [B,TD,H] then e_outputs [B,TD,TE], flattened in order.
// ---------------------------------------------------------------------------
extern "C" void kernel_launch(void* const* d_in, const int* in_sizes, int n_in,
                              void* d_out, int out_size) {
    const float* enc = (const float*)d_in[0];   // [B,TE,H]
    const float* dec = (const float*)d_in[1];   // [B,TD,D]
    const float* Wa  = (const float*)d_in[2];   // [H,H]
    const float* Ua  = (const float*)d_in[3];   // [D,H]
    const float* Va  = (const float*)d_in[4];   // [H,1]

    float* out   = (float*)d_out;
    float* c_out = out;                          // B*TD*H
    float* e_out = out + (size_t)BB * TD * HH;   // B*TD*TE

    proj_kernel<<<BB * TE / 16, 256>>>(enc, Wa, 0);
    proj_kernel<<<BB * TD / 16, 256>>>(dec, Ua, 1);
    score_kernel<<<dim3(TE / TT, TD / TJ, BB), 256>>>(Va, e_out);
    softmax_kernel<<<BB * TD, 256>>>(e_out);
    context_kernel<<<BB * TD / JT, 256>>>(enc, e_out, c_out);
}